// round 8
// baseline (speedup 1.0000x reference)
#include <cuda_runtime.h>

#define BATCH   8
#define NDATA   8192
#define NPOINT  1024
#define NSAMPLE 32
#define CFEAT   64
#define RADIUSF 0.2f
#define T_LOOSE 0.0404f

#define NP_SIZE  (BATCH*NPOINT*NSAMPLE*(3+CFEAT))   /* 17563648 */
#define IDX_OFF  NP_SIZE
#define IDX_SIZE (BATCH*NPOINT*NSAMPLE)             /* 262144 */
#define GX_OFF   (IDX_OFF + IDX_SIZE)
#define GX_SIZE  (BATCH*NPOINT*NSAMPLE*3)           /* 786432 */

#define QB  16   /* queries per block             */
#define WPB 8    /* warps per block (scan chunks) */
#define CHUNK (NDATA/WPB)                           /* 1024 */
#define CAP 64   /* candidate capacity per query  */

#define GA_BLOCKS (NP_SIZE/4/512)                   /* 8576: NP quads, 2/thread */
#define GX_BLOCKS 384                               /* GX tail, 8 elems/thread  */
#define GX_STRIDE (GX_BLOCKS*256)                   /* 98304 */

__device__ float4 g_pts[BATCH*NDATA];   /* (x, y, z, |p|^2) */

__global__ void k_transpose(const float* __restrict__ xyz)
{
    int t = blockIdx.x * blockDim.x + threadIdx.x;
    if (t < BATCH*NDATA) {
        float x = xyz[3*t + 0];
        float y = xyz[3*t + 1];
        float z = xyz[3*t + 2];
        float pp = fmaf(x, x, fmaf(y, y, z*z));
        g_pts[t] = make_float4(x, y, z, pp);
    }
}

__global__ __launch_bounds__(WPB*32)
void k_search(const float* __restrict__ new_xyz, float* __restrict__ out)
{
    __shared__ float s_cd[QB][CAP];
    __shared__ int   s_ci[QB][CAP];
    __shared__ int   s_cnt[QB];
    __shared__ int   s_out[QB][NSAMPLE];
    __shared__ float s_qx[QB], s_qy[QB], s_qz[QB];

    const int b    = blockIdx.y;
    const int w    = threadIdx.x >> 5;
    const int lane = threadIdx.x & 31;
    const int p0   = blockIdx.x * QB;

    if (threadIdx.x < QB) {
        s_cnt[threadIdx.x] = 0;
        const float* qp = new_xyz + ((size_t)b*NPOINT + p0 + threadIdx.x) * 3;
        s_qx[threadIdx.x] = qp[0];
        s_qy[threadIdx.x] = qp[1];
        s_qz[threadIdx.x] = qp[2];
    }
    __syncthreads();

    float nqx[QB], nqy[QB], nqz[QB], qt[QB];
#pragma unroll
    for (int q = 0; q < QB; q++) {
        float cx = s_qx[q], cy = s_qy[q], cz = s_qz[q];
        nqx[q] = -2.0f*cx; nqy[q] = -2.0f*cy; nqz[q] = -2.0f*cz;
        qt[q] = T_LOOSE - fmaf(cx,cx, fmaf(cy,cy, cz*cz));
    }

    const float4* pts = g_pts + b*NDATA;

    const int ptEnd = (w+1)*CHUNK;
    for (int pt = w*CHUNK + lane; pt < ptEnd; pt += 32) {
        float4 P = pts[pt];
        unsigned m = 0;
#pragma unroll
        for (int q = 0; q < QB; q++) {
            float l = fmaf(P.x, nqx[q], fmaf(P.y, nqy[q], fmaf(P.z, nqz[q], P.w)));
            if (l < qt[q]) m |= (1u << q);
        }
        while (m) {
            int q = __ffs(m) - 1;
            m &= m - 1;
            float dx = P.x - s_qx[q];
            float dy = P.y - s_qy[q];
            float dz = P.z - s_qz[q];
            float e = __fadd_rn(__fadd_rn(__fmul_rn(dx,dx), __fmul_rn(dy,dy)),
                                __fmul_rn(dz,dz));
            float d = __fsqrt_rn(e);
            if (d < RADIUSF) {
                int slot = atomicAdd(&s_cnt[q], 1);
                if (slot < CAP) { s_cd[q][slot] = d; s_ci[q][slot] = pt; }
            }
        }
    }
    __syncthreads();

    for (int qq = 0; qq < QB/WPB; qq++) {
        const int q = w*(QB/WPB) + qq;
        const int n = min(s_cnt[q], CAP);
        const int p = p0 + q;

        if (n == 0) {
            float cx = s_qx[q], cy = s_qy[q], cz = s_qz[q];
            float bd = 3.4e38f; int bi = 0;
            for (int pt = lane; pt < NDATA; pt += 32) {
                float4 P = pts[pt];
                float dx = P.x - cx;
                float dy = P.y - cy;
                float dz = P.z - cz;
                float e  = __fadd_rn(__fadd_rn(__fmul_rn(dx,dx), __fmul_rn(dy,dy)),
                                     __fmul_rn(dz,dz));
                if (e < bd) { bd = e; bi = pt; }
            }
#pragma unroll
            for (int off = 16; off >= 1; off >>= 1) {
                float od = __shfl_xor_sync(0xffffffffu, bd, off);
                int   oi = __shfl_xor_sync(0xffffffffu, bi, off);
                if (od < bd || (od == bd && oi < bi)) { bd = od; bi = oi; }
            }
            s_out[q][lane] = bi;
        } else {
            for (int i = lane; i < n; i += 32) {
                float di = s_cd[q][i]; int ii = s_ci[q][i];
                int rank = 0;
                for (int j = 0; j < n; j++) {
                    float dj = s_cd[q][j]; int ij = s_ci[q][j];
                    rank += (dj < di) || (dj == di && ij < ii);
                }
                if (rank < NSAMPLE) s_out[q][rank] = ii;
            }
            __syncwarp();
            int nearest = s_out[q][0];
            if (lane >= n) s_out[q][lane] = nearest;
        }
        __syncwarp();

        out[IDX_OFF + ((size_t)(b*NPOINT + p))*NSAMPLE + lane] = (float)s_out[q][lane];
    }
}

// Output-linear gather: threads own contiguous float4 quads of the new_points
// region -> dense aligned STG.128. id per row fetched via L1 broadcast.
// Tail block-range writes the grouped_xyz region.
__global__ __launch_bounds__(256)
void k_gather(const float* __restrict__ xyz,
              const float* __restrict__ points,
              float* __restrict__ out)
{
    const float* idxf = out + IDX_OFF;
    const int bid = blockIdx.x;

    if (bid < GA_BLOCKS) {
        const int q0 = bid*512 + threadIdx.x;
#pragma unroll
        for (int k = 0; k < 2; k++) {
            const int o  = (q0 + k*256) * 4;
            const int r  = o / 67;
            const int c0 = o - r*67;
            const int r3 = (o + 3) / 67;
            const int id0 = (int)__ldg(&idxf[r]);
            const int id3 = (r3 != r) ? (int)__ldg(&idxf[r3]) : id0;

            float v[4];
#pragma unroll
            for (int j = 0; j < 4; j++) {
                int cc = c0 + j;
                int rr = r, id = id0;
                if (cc >= 67) { cc -= 67; rr = r3; id = id3; }
                const int b = rr >> 15;
                const long base = (long)b*NDATA + id;
                v[j] = (cc < 3) ? __ldg(&xyz[base*3 + cc])
                                : __ldg(&points[base*CFEAT + (cc-3)]);
            }
            *reinterpret_cast<float4*>(out + o) = make_float4(v[0],v[1],v[2],v[3]);
        }
    } else {
        const int t = (bid - GA_BLOCKS)*256 + threadIdx.x;
#pragma unroll
        for (int k = 0; k < 8; k++) {
            const int e = t + k*GX_STRIDE;
            const int r = e / 3;
            const int c = e - r*3;
            const int b = r >> 15;
            const int id = (int)__ldg(&idxf[r]);
            out[GX_OFF + e] = __ldg(&xyz[((long)b*NDATA + id)*3 + c]);
        }
    }
}

extern "C" void kernel_launch(void* const* d_in, const int* in_sizes, int n_in,
                              void* d_out, int out_size)
{
    const float *new_xyz = nullptr, *xyz = nullptr, *points = nullptr;
    for (int i = 0; i < n_in; i++) {
        if      (in_sizes[i] == BATCH*NPOINT*3)     new_xyz = (const float*)d_in[i];
        else if (in_sizes[i] == BATCH*NDATA*3)      xyz     = (const float*)d_in[i];
        else if (in_sizes[i] == BATCH*NDATA*CFEAT)  points  = (const float*)d_in[i];
    }
    float* out = (float*)d_out;

    k_transpose<<<(BATCH*NDATA + 255)/256, 256>>>(xyz);

    dim3 gs(NPOINT/QB, BATCH);
    k_search<<<gs, WPB*32>>>(new_xyz, out);

    k_gather<<<GA_BLOCKS + GX_BLOCKS, 256>>>(xyz, points, out);
}